// round 16
// baseline (speedup 1.0000x reference)
#include <cuda_runtime.h>
#include <cuda_bf16.h>
#include <cuda_fp8.h>
#include <stdint.h>
#include <math.h>

// Problem dims
#define B_   65536
#define D_   1024
#define E_   16
#define H1_  128
#define H2_  64
#define R1_  64
#define R2_  32
#define NEXP (E_ * H1_)          // 2048 expert cols
#define NCAT (NEXP + R1_)        // 2112 live cols
#define NP   2176                // padded to 17*128
#define EPS  1e-5f
#define QSCALE 64.f
#define QINV   (1.f / 64.f)
#define HQ     16.f              // h1 fp8 scale
#define QINV2  (1.f / 1024.f)    // 1/(QSCALE*HQ)

// ---------------- device scratch ----------------
__device__ unsigned char g_x8[(size_t)B_ * D_];          // x e4m3
__device__ unsigned char g_W8[(size_t)NP * D_];          // folded W1, e4m3*64
__device__ float         g_bcat[NP];
__device__ unsigned char g_W28[(size_t)E_ * H2_ * H1_];  // eW2^T e4m3*64 [e][h2][h1]
__device__ float         g_Eo[(size_t)E_ * B_];          // expert outputs [e][b]

// ---------------- asm helpers ----------------
__device__ __forceinline__ void mma16832q(float c[4],
    uint32_t a0, uint32_t a1, uint32_t a2, uint32_t a3,
    uint32_t b0, uint32_t b1) {
  asm volatile(
    "mma.sync.aligned.m16n8k32.row.col.f32.e4m3.e4m3.f32 "
    "{%0,%1,%2,%3},{%4,%5,%6,%7},{%8,%9},{%0,%1,%2,%3};"
    : "+f"(c[0]), "+f"(c[1]), "+f"(c[2]), "+f"(c[3])
    : "r"(a0), "r"(a1), "r"(a2), "r"(a3), "r"(b0), "r"(b1));
}

__device__ __forceinline__ void ldsm4(uint32_t& r0, uint32_t& r1,
                                      uint32_t& r2, uint32_t& r3, uint32_t addr) {
  asm volatile("ldmatrix.sync.aligned.m8n8.x4.shared.b16 {%0,%1,%2,%3},[%4];"
               : "=r"(r0), "=r"(r1), "=r"(r2), "=r"(r3) : "r"(addr));
}

__device__ __forceinline__ void cp_async16(uint32_t saddr, const void* gaddr) {
  asm volatile("cp.async.cg.shared.global [%0],[%1],16;" ::"r"(saddr), "l"(gaddr)
               : "memory");
}
__device__ __forceinline__ void cp_commit() {
  asm volatile("cp.async.commit_group;" ::: "memory");
}
__device__ __forceinline__ void cp_wait1() {
  asm volatile("cp.async.wait_group 1;" ::: "memory");
}

__device__ __forceinline__ uint32_t smem_u32(const void* p) {
  uint32_t a;
  asm("{.reg .u64 t; cvta.to.shared.u64 t, %1; cvt.u32.u64 %0, t;}"
      : "=r"(a) : "l"(p));
  return a;
}

// swizzled byte offset inside 128-byte-row tiles (8 x 16B chunks)
__device__ __forceinline__ uint32_t swz64(uint32_t row, uint32_t chunk) {
  return row * 128u + ((chunk ^ (row & 7u)) << 4);
}

__device__ __forceinline__ uint32_t pack_relu(float a, float b) {
  __nv_bfloat162 t = __floats2bfloat162_rn(fmaxf(a, 0.f), fmaxf(b, 0.f));
  return *(uint32_t*)&t;
}

// ======== Merged preprocessing: fold | w2t | cvt (long blocks first) =====
#define PREP_FOLD NP                          // 2176
#define PREP_W2T  (E_ * H1_ * H2_ / 256)      // 512
#define PREP_CVT  16384                       // 4 float4 per thread

__global__ __launch_bounds__(256) void k_prep(
    const float* __restrict__ x,
    const float* __restrict__ rg, const float* __restrict__ rb,
    const float* __restrict__ rm, const float* __restrict__ rv,
    const float* __restrict__ rW1, const float* __restrict__ rb1,
    const float* __restrict__ eg, const float* __restrict__ ebt,
    const float* __restrict__ em, const float* __restrict__ ev,
    const float* __restrict__ eW1, const float* __restrict__ eb1,
    const float* __restrict__ eW2) {
  const int bid = blockIdx.x;
  const int tid = threadIdx.x;

  if (bid < PREP_FOLD) {
    int n = bid;
    __shared__ float red[256];
    float acc = 0.f;
    if (n < NEXP) {
      int e = n >> 7, h = n & 127;
      const float* W = eW1 + (size_t)e * D_ * H1_;
      const float* Gg = eg + (size_t)e * D_;
      const float* Gb = ebt + (size_t)e * D_;
      const float* Gm = em + (size_t)e * D_;
      const float* Gv = ev + (size_t)e * D_;
      for (int k = tid; k < D_; k += 256) {
        float sc = Gg[k] * rsqrtf(Gv[k] + EPS);
        float sh = Gb[k] - Gm[k] * sc;
        float wv = W[(size_t)k * H1_ + h];
        g_W8[(size_t)n * D_ + k] = (unsigned char)__nv_cvt_float_to_fp8(
            QSCALE * wv * sc, __NV_SATFINITE, __NV_E4M3);
        acc += sh * wv;
      }
    } else if (n < NCAT) {
      int rn = n - NEXP;
      for (int k = tid; k < D_; k += 256) {
        float sc = rg[k] * rsqrtf(rv[k] + EPS);
        float sh = rb[k] - rm[k] * sc;
        float wv = rW1[(size_t)k * R1_ + rn];
        g_W8[(size_t)n * D_ + k] = (unsigned char)__nv_cvt_float_to_fp8(
            QSCALE * wv * sc, __NV_SATFINITE, __NV_E4M3);
        acc += sh * wv;
      }
    } else {
      for (int k = tid; k < D_; k += 256)
        g_W8[(size_t)n * D_ + k] = 0;
    }
    red[tid] = acc;
    __syncthreads();
    for (int s = 128; s > 0; s >>= 1) {
      if (tid < s) red[tid] += red[tid + s];
      __syncthreads();
    }
    if (tid == 0) {
      float base = 0.f;
      if (n < NEXP) base = eb1[(size_t)(n >> 7) * H1_ + (n & 127)];
      else if (n < NCAT) base = rb1[n - NEXP];
      g_bcat[n] = base + red[0];
    }
    return;
  }
  if (bid < PREP_FOLD + PREP_W2T) {
    int idx = (bid - PREP_FOLD) * 256 + tid;  // < 131072, eW2[e][h1][h2]
    int e = idx >> 13;
    int r = idx & 8191;
    int k = r >> 6;   // h1
    int n = r & 63;   // h2
    g_W28[((size_t)e * H2_ + n) * H1_ + k] = (unsigned char)__nv_cvt_float_to_fp8(
        QSCALE * eW2[idx], __NV_SATFINITE, __NV_E4M3);
    return;
  }
  {
    size_t base = (size_t)(bid - PREP_FOLD - PREP_W2T) * 256 + tid;
#pragma unroll
    for (int kq = 0; kq < 4; kq++) {
      size_t i = base + (size_t)kq * (PREP_CVT * 256);
      float4 v = ((const float4*)x)[i];
      __nv_fp8x2_storage_t p0 = __nv_cvt_float2_to_fp8x2(
          make_float2(v.x, v.y), __NV_SATFINITE, __NV_E4M3);
      __nv_fp8x2_storage_t p1 = __nv_cvt_float2_to_fp8x2(
          make_float2(v.z, v.w), __NV_SATFINITE, __NV_E4M3);
      ((uint32_t*)g_x8)[i] = (uint32_t)p0 | ((uint32_t)p1 << 16);
    }
  }
}

// ======== Uniform fp8 GEMM1 + fp8 GEMM2 + L3 | router GEMM+MLP tail ======
// All 17 bx: BM=128 BN=128 BK=128 fp8, 8 iters (fully unrolled), 3-stage
// cp.async, 128 threads (2x2 warps, warp tile 64x64). smem 98688B -> 2 CTAs/SM.
#define SM_A    0u        // 3 x 16384
#define SM_B    49152u    // 3 x 16384
#define SM_W2   49152u    // 8KB fp8
#define SM_H2   57344u    // 16KB bf16 (ends 73728)
#define SM_EW3  98304u
#define SM_EB3  98560u
#define SM_TOT  98688u
// router-tail scratch (A region dead): hs floats [128][66] @0 (33792B),
// rW2 @34816 (8KB), rW3 @43008 (2KB), rb2 @45056, rb3 @45184 — all < 49152
#define SM_HS   0u
#define SM_RW2  34816u
#define SM_RW3  43008u
#define SM_RB2  45056u
#define SM_RB3  45184u
#define HS_STR  66

__global__ __launch_bounds__(128, 2) void k_gemm_f(
    const float* __restrict__ eb2, const float* __restrict__ eW3,
    const float* __restrict__ eb3,
    const float* __restrict__ rW2, const float* __restrict__ rb2,
    const float* __restrict__ rW3, const float* __restrict__ rb3,
    float* __restrict__ out) {
  extern __shared__ __align__(1024) char smem[];
  const uint32_t sb = smem_u32(smem);
  const int bx = blockIdx.x;            // 0..15 experts, 16 = router(+pad)
  const int m0 = blockIdx.y * 128;
  const int n0 = bx * 128;
  const int tid = threadIdx.x;
  const int wid = tid >> 5, lane = tid & 31;
  const int g = lane >> 2, t = lane & 3;
  const int mW = wid >> 1, nW = wid & 1;       // 2x2 warp grid
  const int lr = lane & 15, lc = lane >> 4;

  float* ew3_s = (float*)(smem + SM_EW3);
  float* eb3_s = (float*)(smem + SM_EB3);
  if (bx < E_) {
    if (tid < H2_) ew3_s[tid] = eW3[bx * H2_ + tid];
    if (tid == 0) eb3_s[0] = eb3[bx];
  }

  float acc[4][8][4];
#pragma unroll
  for (int i = 0; i < 4; i++)
#pragma unroll
    for (int j = 0; j < 8; j++)
#pragma unroll
      for (int c = 0; c < 4; c++) acc[i][j][c] = 0.f;

  // hoisted global row bases for this block's tiles
  const unsigned char* gA = g_x8 + ((size_t)m0 + (tid >> 3)) * D_;
  const unsigned char* gB = g_W8 + ((size_t)n0 + (tid >> 3)) * D_;
  const uint32_t so0 = swz64(tid >> 3, tid & 7);   // per-thread swizzle base
  const int ch16 = (tid & 7) * 16;

  // stage: A 128x128 fp8 (16KB) + B 128x128 fp8 (16KB); rows tid>>3 + 16*i
  auto load_stage = [&](uint32_t st, int k0) {
#pragma unroll
    for (int i = 0; i < 8; i++) {
      // row advances by 16 per i: swz64(row+16, ch) = swz64(row,ch) + 2048
      uint32_t so = so0 + (uint32_t)i * 2048u;
      cp_async16(sb + SM_A + st * 16384u + so, gA + (size_t)i * 16 * D_ + k0 + ch16);
      cp_async16(sb + SM_B + st * 16384u + so, gB + (size_t)i * 16 * D_ + k0 + ch16);
    }
  };

  load_stage(0, 0);   cp_commit();
  load_stage(1, 128); cp_commit();

  const int NITER = D_ / 128;  // 8
#pragma unroll
  for (int it = 0; it < NITER; ++it) {
    cp_wait1();
    __syncthreads();
    if (it + 2 < NITER) load_stage((uint32_t)((it + 2) % 3), (it + 2) * 128);
    cp_commit();
    const uint32_t sAb = sb + SM_A + (uint32_t)(it % 3) * 16384u;
    const uint32_t sBb = sb + SM_B + (uint32_t)(it % 3) * 16384u;
#pragma unroll
    for (int kk = 0; kk < 4; ++kk) {     // 4 k32-steps
      uint32_t a[4][4], bfr[4][4];
#pragma unroll
      for (int i = 0; i < 4; i++)
        ldsm4(a[i][0], a[i][1], a[i][2], a[i][3],
              sAb + swz64(mW * 64 + i * 16 + lr, 2 * kk + lc));
#pragma unroll
      for (int jj = 0; jj < 4; jj++)
        ldsm4(bfr[jj][0], bfr[jj][1], bfr[jj][2], bfr[jj][3],
              sBb + swz64(nW * 64 + jj * 16 + lr, 2 * kk + lc));
#pragma unroll
      for (int i = 0; i < 4; i++)
#pragma unroll
        for (int j = 0; j < 8; j++)
          mma16832q(acc[i][j], a[i][0], a[i][1], a[i][2], a[i][3],
                    bfr[j >> 1][j & 1], bfr[j >> 1][(j & 1) + 2]);
    }
  }
  __syncthreads();   // mainloop smem now dead

  if (bx < E_) {
    // ---- h1 = relu(acc/64 + bias) * 16 -> H1s fp8 (A region), swz64 ----
#pragma unroll
    for (int i = 0; i < 4; i++) {
#pragma unroll
      for (int j = 0; j < 8; j++) {
        int row = mW * 64 + i * 16 + g;
        int col = nW * 64 + j * 8 + 2 * t;
        float b0v = g_bcat[n0 + col], b1v = g_bcat[n0 + col + 1];
        float f0 = fmaxf(fmaf(acc[i][j][0], QINV, b0v), 0.f) * HQ;
        float f1 = fmaxf(fmaf(acc[i][j][1], QINV, b1v), 0.f) * HQ;
        float f2 = fmaxf(fmaf(acc[i][j][2], QINV, b0v), 0.f) * HQ;
        float f3 = fmaxf(fmaf(acc[i][j][3], QINV, b1v), 0.f) * HQ;
        *(uint16_t*)(smem + SM_A + swz64(row, col >> 4) + (col & 15)) =
            (uint16_t)__nv_cvt_float2_to_fp8x2(make_float2(f0, f1),
                                               __NV_SATFINITE, __NV_E4M3);
        *(uint16_t*)(smem + SM_A + swz64(row + 8, col >> 4) + (col & 15)) =
            (uint16_t)__nv_cvt_float2_to_fp8x2(make_float2(f2, f3),
                                               __NV_SATFINITE, __NV_E4M3);
      }
    }
    // ---- stage W2[e] (64x128 fp8) -> W2s, swz64 ----
#pragma unroll
    for (int i = 0; i < 4; i++) {
      int idx = tid + 128 * i;          // 512 = 64 rows x 8 chunks
      int row = idx >> 3, ch = idx & 7;
      uint4 v = *(const uint4*)(g_W28 + ((size_t)bx * H2_ + row) * H1_ + ch * 16);
      *(uint4*)(smem + SM_W2 + swz64(row, ch)) = v;
    }
    __syncthreads();

    // ---- GEMM2 fp8: h2 = relu(H1s @ W2s^T /1024 + eb2) -> H2s bf16 ----
    float acc2[2][8][4];
#pragma unroll
    for (int i = 0; i < 2; i++)
#pragma unroll
      for (int j = 0; j < 8; j++)
#pragma unroll
        for (int c = 0; c < 4; c++) acc2[i][j][c] = 0.f;

#pragma unroll
    for (int ks = 0; ks < 4; ++ks) {     // 4 k32-steps over K=128
      uint32_t a[2][4], bfr[4][4];
#pragma unroll
      for (int i = 0; i < 2; i++)
        ldsm4(a[i][0], a[i][1], a[i][2], a[i][3],
              sb + SM_A + swz64(wid * 32 + i * 16 + lr, 2 * ks + lc));
#pragma unroll
      for (int jj = 0; jj < 4; jj++)
        ldsm4(bfr[jj][0], bfr[jj][1], bfr[jj][2], bfr[jj][3],
              sb + SM_W2 + swz64(jj * 16 + lr, 2 * ks + lc));
#pragma unroll
      for (int i = 0; i < 2; i++)
#pragma unroll
        for (int j = 0; j < 8; j++)
          mma16832q(acc2[i][j], a[i][0], a[i][1], a[i][2], a[i][3],
                    bfr[j >> 1][j & 1], bfr[j >> 1][(j & 1) + 2]);
    }
#pragma unroll
    for (int i = 0; i < 2; i++) {
#pragma unroll
      for (int j = 0; j < 8; j++) {
        int row = wid * 32 + i * 16 + g;
        int col = j * 8 + 2 * t;
        float b0v = eb2[bx * H2_ + col], b1v = eb2[bx * H2_ + col + 1];
        *(uint32_t*)(smem + SM_H2 + swz64(row, col >> 3) + (col & 7) * 2) =
            pack_relu(fmaf(acc2[i][j][0], QINV2, b0v),
                      fmaf(acc2[i][j][1], QINV2, b1v));
        *(uint32_t*)(smem + SM_H2 + swz64(row + 8, col >> 3) + (col & 7) * 2) =
            pack_relu(fmaf(acc2[i][j][2], QINV2, b0v),
                      fmaf(acc2[i][j][3], QINV2, b1v));
      }
    }
    __syncthreads();

    // ---- expert L3: per-row dot64 + sigmoid -> g_Eo[e][b] ----
    {
      float logit = eb3_s[0];
#pragma unroll
      for (int ch = 0; ch < 8; ch++) {
        uint4 v = *(const uint4*)(smem + SM_H2 + swz64(tid, ch));
        const __nv_bfloat162* p = (const __nv_bfloat162*)&v;
#pragma unroll
        for (int q = 0; q < 4; q++) {
          float2 f = __bfloat1622float2(p[q]);
          logit += f.x * ew3_s[ch * 8 + 2 * q] + f.y * ew3_s[ch * 8 + 2 * q + 1];
        }
      }
      g_Eo[(size_t)bx * B_ + m0 + tid] = 1.f / (1.f + __expf(-logit));
    }
  } else {
    // ---- router epilogue: cols [0,64) live (nW==0 warps) -> hs fp32 ----
    float* hs = (float*)(smem + SM_HS);
    if (nW == 0) {
#pragma unroll
      for (int i = 0; i < 4; i++) {
#pragma unroll
        for (int j = 0; j < 8; j++) {
          int row = mW * 64 + i * 16 + g;
          int col = j * 8 + 2 * t;
          float b0v = g_bcat[n0 + col], b1v = g_bcat[n0 + col + 1];
          hs[row * HS_STR + col] = fmaxf(fmaf(acc[i][j][0], QINV, b0v), 0.f);
          hs[row * HS_STR + col + 1] = fmaxf(fmaf(acc[i][j][1], QINV, b1v), 0.f);
          hs[(row + 8) * HS_STR + col] =
              fmaxf(fmaf(acc[i][j][2], QINV, b0v), 0.f);
          hs[(row + 8) * HS_STR + col + 1] =
              fmaxf(fmaf(acc[i][j][3], QINV, b1v), 0.f);
        }
      }
    }
    // ---- load router tail weights ----
    float* rW2_s = (float*)(smem + SM_RW2);
    float* rW3_s = (float*)(smem + SM_RW3);
    float* rb2_s = (float*)(smem + SM_RB2);
    float* rb3_s = (float*)(smem + SM_RB3);
#pragma unroll
    for (int i = 0; i < 16; i++) rW2_s[tid + 128 * i] = rW2[tid + 128 * i];
#pragma unroll
    for (int i = 0; i < 4; i++) rW3_s[tid + 128 * i] = rW3[tid + 128 * i];
    if (tid < R2_) rb2_s[tid] = rb2[tid];
    if (tid < E_) rb3_s[tid] = rb3[tid];
    __syncthreads();

    // ---- per-row MLP tail + softmax -> out routing_weights ----
    for (int rr = 0; rr < 32; ++rr) {
      int row = wid * 32 + rr;
      const float* hrow = hs + row * HS_STR;
      float d1 = rb2_s[lane];
#pragma unroll
      for (int k = 0; k < R1_; k++) d1 += hrow[k] * rW2_s[k * R2_ + lane];
      d1 = fmaxf(d1, 0.f);

      float d2 = (lane < E_) ? rb3_s[lane] : 0.f;
#pragma unroll
      for (int k = 0; k < R2_; k++) {
        float v = __shfl_sync(0xffffffffu, d1, k);
        if (lane < E_) d2 += v * rW3_s[k * E_ + lane];
      }
      float mx = d2;
#pragma unroll
      for (int off = 8; off > 0; off >>= 1)
        mx = fmaxf(mx, __shfl_xor_sync(0xffffffffu, mx, off, 16));
      float ex = __expf(d2 - mx);
      float s = ex;
#pragma unroll
      for (int off = 8; off > 0; off >>= 1)
        s += __shfl_xor_sync(0xffffffffu, s, off, 16);
      if (lane < E_)
        out[(size_t)B_ + (size_t)(m0 + row) * E_ + lane] = ex / s;
    }
  }
}

// ---------------- k_mix: pred = sum_e rw*eo; write expert_outputs --------
__global__ __launch_bounds__(256) void k_mix(float* __restrict__ out) {
  int b = blockIdx.x * 256 + threadIdx.x;
  const float4* rwp = (const float4*)(out + (size_t)B_ + (size_t)b * E_);
  float4 r0 = rwp[0], r1 = rwp[1], r2 = rwp[2], r3 = rwp[3];
  float eo[E_];
#pragma unroll
  for (int e = 0; e < E_; e++) eo[e] = g_Eo[(size_t)e * B_ + b];
  float p = r0.x * eo[0] + r0.y * eo[1] + r0.z * eo[2] + r0.w * eo[3] +
            r1.x * eo[4] + r1.y * eo[5] + r1.z * eo[6] + r1.w * eo[7] +
            r2.x * eo[8] + r2.y * eo[9] + r2.z * eo[10] + r2.w * eo[11] +
            r3.x * eo[12] + r3.y * eo[13] + r3.z * eo[14] + r3.w * eo[15];
  out[b] = p;
  float4* eop = (float4*)(out + (size_t)B_ + (size_t)B_ * E_ + (size_t)b * E_);
#pragma unroll
  for (int q = 0; q < 4; q++)
    eop[q] = make_float4(eo[4 * q], eo[4 * q + 1], eo[4 * q + 2], eo[4 * q + 3]);
}

// ---------------- launch ----------------
extern "C" void kernel_launch(void* const* d_in, const int* in_sizes, int n_in,
                              void* d_out, int out_size) {
  const float* x     = (const float*)d_in[0];
  const float* rg    = (const float*)d_in[1];
  const float* rbta  = (const float*)d_in[2];
  const float* rm    = (const float*)d_in[3];
  const float* rv    = (const float*)d_in[4];
  const float* rW1   = (const float*)d_in[5];
  const float* rb1   = (const float*)d_in[6];
  const float* rW2   = (const float*)d_in[7];
  const float* rb2   = (const float*)d_in[8];
  const float* rW3   = (const float*)d_in[9];
  const float* rb3   = (const float*)d_in[10];
  const float* eg    = (const float*)d_in[11];
  const float* ebt   = (const float*)d_in[12];
  const float* em    = (const float*)d_in[13];
  const float* ev    = (const float*)d_in[14];
  const float* eW1   = (const float*)d_in[15];
  const float* eb1   = (const float*)d_in[16];
  const float* eW2   = (const float*)d_in[17];
  const float* eb2   = (const float*)d_in[18];
  const float* eW3   = (const float*)d_in[19];
  const float* eb3   = (const float*)d_in[20];
  float* out = (float*)d_out;

  cudaFuncSetAttribute(k_gemm_f, cudaFuncAttributeMaxDynamicSharedMemorySize,
                       SM_TOT);

  k_prep<<<PREP_FOLD + PREP_W2T + PREP_CVT, 256>>>(
      x, rg, rbta, rm, rv, rW1, rb1, eg, ebt, em, ev, eW1, eb1, eW2);
  k_gemm_f<<<dim3(E_ + 1, B_ / 128), 128, SM_TOT>>>(eb2, eW3, eb3,
                                                    rW2, rb2, rW3, rb3, out);
  k_mix<<<B_ / 256, 256>>>(out);
}

// round 17
// speedup vs baseline: 1.4493x; 1.4493x over previous
#include <cuda_runtime.h>
#include <cuda_bf16.h>
#include <cuda_fp8.h>
#include <stdint.h>
#include <math.h>

// Problem dims
#define B_   65536
#define D_   1024
#define E_   16
#define H1_  128
#define H2_  64
#define R1_  64
#define R2_  32
#define NEXP (E_ * H1_)          // 2048 expert cols
#define NCAT (NEXP + R1_)        // 2112 live cols
#define NP   2176                // padded to 17*128
#define EPS  1e-5f
#define QSCALE 64.f
#define QINV   (1.f / 64.f)
#define HQ     16.f              // h1 fp8 scale
#define QINV2  (1.f / 1024.f)    // 1/(QSCALE*HQ)

// ---------------- device scratch ----------------
__device__ unsigned char g_x8[(size_t)B_ * D_];          // x e4m3
__device__ unsigned char g_W8[(size_t)NP * D_];          // folded W1, e4m3*64
__device__ float         g_bcat[NP];
__device__ unsigned char g_W28[(size_t)E_ * H2_ * H1_];  // eW2^T e4m3*64 [e][h2][h1]
__device__ float         g_Eo[(size_t)E_ * B_];          // expert outputs [e][b]

// ---------------- asm helpers ----------------
__device__ __forceinline__ void mma16832q(float c[4],
    uint32_t a0, uint32_t a1, uint32_t a2, uint32_t a3,
    uint32_t b0, uint32_t b1) {
  asm volatile(
    "mma.sync.aligned.m16n8k32.row.col.f32.e4m3.e4m3.f32 "
    "{%0,%1,%2,%3},{%4,%5,%6,%7},{%8,%9},{%0,%1,%2,%3};"
    : "+f"(c[0]), "+f"(c[1]), "+f"(c[2]), "+f"(c[3])
    : "r"(a0), "r"(a1), "r"(a2), "r"(a3), "r"(b0), "r"(b1));
}

__device__ __forceinline__ void ldsm4(uint32_t& r0, uint32_t& r1,
                                      uint32_t& r2, uint32_t& r3, uint32_t addr) {
  asm volatile("ldmatrix.sync.aligned.m8n8.x4.shared.b16 {%0,%1,%2,%3},[%4];"
               : "=r"(r0), "=r"(r1), "=r"(r2), "=r"(r3) : "r"(addr));
}

__device__ __forceinline__ void cp_async16(uint32_t saddr, const void* gaddr) {
  asm volatile("cp.async.cg.shared.global [%0],[%1],16;" ::"r"(saddr), "l"(gaddr)
               : "memory");
}
__device__ __forceinline__ void cp_commit() {
  asm volatile("cp.async.commit_group;" ::: "memory");
}
__device__ __forceinline__ void cp_wait1() {
  asm volatile("cp.async.wait_group 1;" ::: "memory");
}

__device__ __forceinline__ uint32_t smem_u32(const void* p) {
  uint32_t a;
  asm("{.reg .u64 t; cvta.to.shared.u64 t, %1; cvt.u32.u64 %0, t;}"
      : "=r"(a) : "l"(p));
  return a;
}

// swizzled byte offset inside 128-byte-row tiles (8 x 16B chunks)
__device__ __forceinline__ uint32_t swz64(uint32_t row, uint32_t chunk) {
  return row * 128u + ((chunk ^ (row & 7u)) << 4);
}

__device__ __forceinline__ uint32_t pack_relu(float a, float b) {
  __nv_bfloat162 t = __floats2bfloat162_rn(fmaxf(a, 0.f), fmaxf(b, 0.f));
  return *(uint32_t*)&t;
}

// ======== Merged preprocessing: fold | w2t | cvt (long blocks first) =====
#define PREP_FOLD NP                          // 2176
#define PREP_W2T  (E_ * H1_ * H2_ / 256)      // 512
#define PREP_CVT  16384                       // 4 float4 per thread

__global__ __launch_bounds__(256) void k_prep(
    const float* __restrict__ x,
    const float* __restrict__ rg, const float* __restrict__ rb,
    const float* __restrict__ rm, const float* __restrict__ rv,
    const float* __restrict__ rW1, const float* __restrict__ rb1,
    const float* __restrict__ eg, const float* __restrict__ ebt,
    const float* __restrict__ em, const float* __restrict__ ev,
    const float* __restrict__ eW1, const float* __restrict__ eb1,
    const float* __restrict__ eW2) {
  const int bid = blockIdx.x;
  const int tid = threadIdx.x;

  if (bid < PREP_FOLD) {
    int n = bid;
    __shared__ float red[256];
    float acc = 0.f;
    if (n < NEXP) {
      int e = n >> 7, h = n & 127;
      const float* W = eW1 + (size_t)e * D_ * H1_;
      const float* Gg = eg + (size_t)e * D_;
      const float* Gb = ebt + (size_t)e * D_;
      const float* Gm = em + (size_t)e * D_;
      const float* Gv = ev + (size_t)e * D_;
      for (int k = tid; k < D_; k += 256) {
        float sc = Gg[k] * rsqrtf(Gv[k] + EPS);
        float sh = Gb[k] - Gm[k] * sc;
        float wv = W[(size_t)k * H1_ + h];
        g_W8[(size_t)n * D_ + k] = (unsigned char)__nv_cvt_float_to_fp8(
            QSCALE * wv * sc, __NV_SATFINITE, __NV_E4M3);
        acc += sh * wv;
      }
    } else if (n < NCAT) {
      int rn = n - NEXP;
      for (int k = tid; k < D_; k += 256) {
        float sc = rg[k] * rsqrtf(rv[k] + EPS);
        float sh = rb[k] - rm[k] * sc;
        float wv = rW1[(size_t)k * R1_ + rn];
        g_W8[(size_t)n * D_ + k] = (unsigned char)__nv_cvt_float_to_fp8(
            QSCALE * wv * sc, __NV_SATFINITE, __NV_E4M3);
        acc += sh * wv;
      }
    } else {
      for (int k = tid; k < D_; k += 256)
        g_W8[(size_t)n * D_ + k] = 0;
    }
    red[tid] = acc;
    __syncthreads();
    for (int s = 128; s > 0; s >>= 1) {
      if (tid < s) red[tid] += red[tid + s];
      __syncthreads();
    }
    if (tid == 0) {
      float base = 0.f;
      if (n < NEXP) base = eb1[(size_t)(n >> 7) * H1_ + (n & 127)];
      else if (n < NCAT) base = rb1[n - NEXP];
      g_bcat[n] = base + red[0];
    }
    return;
  }
  if (bid < PREP_FOLD + PREP_W2T) {
    int idx = (bid - PREP_FOLD) * 256 + tid;  // < 131072, eW2[e][h1][h2]
    int e = idx >> 13;
    int r = idx & 8191;
    int k = r >> 6;   // h1
    int n = r & 63;   // h2
    g_W28[((size_t)e * H2_ + n) * H1_ + k] = (unsigned char)__nv_cvt_float_to_fp8(
        QSCALE * eW2[idx], __NV_SATFINITE, __NV_E4M3);
    return;
  }
  {
    size_t base = (size_t)(bid - PREP_FOLD - PREP_W2T) * 256 + tid;
#pragma unroll
    for (int kq = 0; kq < 4; kq++) {
      size_t i = base + (size_t)kq * (PREP_CVT * 256);
      float4 v = ((const float4*)x)[i];
      __nv_fp8x2_storage_t p0 = __nv_cvt_float2_to_fp8x2(
          make_float2(v.x, v.y), __NV_SATFINITE, __NV_E4M3);
      __nv_fp8x2_storage_t p1 = __nv_cvt_float2_to_fp8x2(
          make_float2(v.z, v.w), __NV_SATFINITE, __NV_E4M3);
      ((uint32_t*)g_x8)[i] = (uint32_t)p0 | ((uint32_t)p1 << 16);
    }
  }
}

// ======== Uniform fp8 GEMM1 + fp8 GEMM2 + L3 | router GEMM+MLP tail ======
// All 17 bx: BM=128 BN=128 BK=128 fp8, 8 iters, 3-stage cp.async,
// 128 threads (2x2 warps, warp tile 64x64). smem 98688B -> 2 CTAs/SM.
// Expert epilogue: H1s fp8 (16KB @A), W2s fp8 (8KB @B), H2s bf16 (16KB @B+8K),
//                  fp8 GEMM2 (K=128, 4 k32-steps), L3 -> g_Eo.
#define SM_A    0u        // 3 x 16384
#define SM_B    49152u    // 3 x 16384
#define SM_W2   49152u    // 8KB fp8
#define SM_H2   57344u    // 16KB bf16 (ends 73728)
#define SM_EW3  98304u
#define SM_EB3  98560u
#define SM_TOT  98688u
// router-tail scratch (A region dead): hs floats [128][66] @0 (33792B),
// rW2 @34816 (8KB), rW3 @43008 (2KB), rb2 @45056, rb3 @45184 — all < 49152
#define SM_HS   0u
#define SM_RW2  34816u
#define SM_RW3  43008u
#define SM_RB2  45056u
#define SM_RB3  45184u
#define HS_STR  66

__global__ __launch_bounds__(128, 2) void k_gemm_f(
    const float* __restrict__ eb2, const float* __restrict__ eW3,
    const float* __restrict__ eb3,
    const float* __restrict__ rW2, const float* __restrict__ rb2,
    const float* __restrict__ rW3, const float* __restrict__ rb3,
    float* __restrict__ out) {
  extern __shared__ __align__(1024) char smem[];
  const uint32_t sb = smem_u32(smem);
  const int bx = blockIdx.x;            // 0..15 experts, 16 = router(+pad)
  const int m0 = blockIdx.y * 128;
  const int n0 = bx * 128;
  const int tid = threadIdx.x;
  const int wid = tid >> 5, lane = tid & 31;
  const int g = lane >> 2, t = lane & 3;
  const int mW = wid >> 1, nW = wid & 1;       // 2x2 warp grid
  const int lr = lane & 15, lc = lane >> 4;

  float* ew3_s = (float*)(smem + SM_EW3);
  float* eb3_s = (float*)(smem + SM_EB3);
  if (bx < E_) {
    if (tid < H2_) ew3_s[tid] = eW3[bx * H2_ + tid];
    if (tid == 0) eb3_s[0] = eb3[bx];
  }

  float acc[4][8][4];
#pragma unroll
  for (int i = 0; i < 4; i++)
#pragma unroll
    for (int j = 0; j < 8; j++)
#pragma unroll
      for (int c = 0; c < 4; c++) acc[i][j][c] = 0.f;

  // stage: A 128x128 fp8 (16KB) + B 128x128 fp8 (16KB); 128B rows, swz64
  auto load_stage = [&](int st, int k0) {
#pragma unroll
    for (int i = 0; i < 8; i++) {
      int idx = tid + 128 * i;          // 1024 chunk-ops per operand
      int row = idx >> 3, ch = idx & 7;
      uint32_t so = swz64(row, ch);
      cp_async16(sb + SM_A + st * 16384u + so,
                 g_x8 + (size_t)(m0 + row) * D_ + k0 + ch * 16);
      cp_async16(sb + SM_B + st * 16384u + so,
                 g_W8 + (size_t)(n0 + row) * D_ + k0 + ch * 16);
    }
  };

  load_stage(0, 0);   cp_commit();
  load_stage(1, 128); cp_commit();

  const int NITER = D_ / 128;  // 8
  for (int it = 0; it < NITER; ++it) {
    cp_wait1();
    __syncthreads();
    if (it + 2 < NITER) load_stage((it + 2) % 3, (it + 2) * 128);
    cp_commit();
    const uint32_t sAb = sb + SM_A + (uint32_t)(it % 3) * 16384u;
    const uint32_t sBb = sb + SM_B + (uint32_t)(it % 3) * 16384u;
#pragma unroll
    for (int kk = 0; kk < 4; ++kk) {     // 4 k32-steps
      uint32_t a[4][4], bfr[4][4];
#pragma unroll
      for (int i = 0; i < 4; i++)
        ldsm4(a[i][0], a[i][1], a[i][2], a[i][3],
              sAb + swz64(mW * 64 + i * 16 + lr, 2 * kk + lc));
#pragma unroll
      for (int jj = 0; jj < 4; jj++)
        ldsm4(bfr[jj][0], bfr[jj][1], bfr[jj][2], bfr[jj][3],
              sBb + swz64(nW * 64 + jj * 16 + lr, 2 * kk + lc));
#pragma unroll
      for (int i = 0; i < 4; i++)
#pragma unroll
        for (int j = 0; j < 8; j++)
          mma16832q(acc[i][j], a[i][0], a[i][1], a[i][2], a[i][3],
                    bfr[j >> 1][j & 1], bfr[j >> 1][(j & 1) + 2]);
    }
  }
  __syncthreads();   // mainloop smem now dead

  if (bx < E_) {
    // ---- h1 = relu(acc/64 + bias) * 16 -> H1s fp8 (A region), swz64 ----
#pragma unroll
    for (int i = 0; i < 4; i++) {
#pragma unroll
      for (int j = 0; j < 8; j++) {
        int row = mW * 64 + i * 16 + g;
        int col = nW * 64 + j * 8 + 2 * t;
        float b0v = g_bcat[n0 + col], b1v = g_bcat[n0 + col + 1];
        float f0 = fmaxf(fmaf(acc[i][j][0], QINV, b0v), 0.f) * HQ;
        float f1 = fmaxf(fmaf(acc[i][j][1], QINV, b1v), 0.f) * HQ;
        float f2 = fmaxf(fmaf(acc[i][j][2], QINV, b0v), 0.f) * HQ;
        float f3 = fmaxf(fmaf(acc[i][j][3], QINV, b1v), 0.f) * HQ;
        *(uint16_t*)(smem + SM_A + swz64(row, col >> 4) + (col & 15)) =
            (uint16_t)__nv_cvt_float2_to_fp8x2(make_float2(f0, f1),
                                               __NV_SATFINITE, __NV_E4M3);
        *(uint16_t*)(smem + SM_A + swz64(row + 8, col >> 4) + (col & 15)) =
            (uint16_t)__nv_cvt_float2_to_fp8x2(make_float2(f2, f3),
                                               __NV_SATFINITE, __NV_E4M3);
      }
    }
    // ---- stage W2[e] (64x128 fp8) -> W2s, swz64 ----
#pragma unroll
    for (int i = 0; i < 4; i++) {
      int idx = tid + 128 * i;          // 512 = 64 rows x 8 chunks
      int row = idx >> 3, ch = idx & 7;
      uint4 v = *(const uint4*)(g_W28 + ((size_t)bx * H2_ + row) * H1_ + ch * 16);
      *(uint4*)(smem + SM_W2 + swz64(row, ch)) = v;
    }
    __syncthreads();

    // ---- GEMM2 fp8: h2 = relu(H1s @ W2s^T /1024 + eb2) -> H2s bf16 ----
    float acc2[2][8][4];
#pragma unroll
    for (int i = 0; i < 2; i++)
#pragma unroll
      for (int j = 0; j < 8; j++)
#pragma unroll
        for (int c = 0; c < 4; c++) acc2[i][j][c] = 0.f;

#pragma unroll
    for (int ks = 0; ks < 4; ++ks) {     // 4 k32-steps over K=128
      uint32_t a[2][4], bfr[4][4];
#pragma unroll
      for (int i = 0; i < 2; i++)
        ldsm4(a[i][0], a[i][1], a[i][2], a[i][3],
              sb + SM_A + swz64(wid * 32 + i * 16 + lr, 2 * ks + lc));
#pragma unroll
      for (int jj = 0; jj < 4; jj++)
        ldsm4(bfr[jj][0], bfr[jj][1], bfr[jj][2], bfr[jj][3],
              sb + SM_W2 + swz64(jj * 16 + lr, 2 * ks + lc));
#pragma unroll
      for (int i = 0; i < 2; i++)
#pragma unroll
        for (int j = 0; j < 8; j++)
          mma16832q(acc2[i][j], a[i][0], a[i][1], a[i][2], a[i][3],
                    bfr[j >> 1][j & 1], bfr[j >> 1][(j & 1) + 2]);
    }
#pragma unroll
    for (int i = 0; i < 2; i++) {
#pragma unroll
      for (int j = 0; j < 8; j++) {
        int row = wid * 32 + i * 16 + g;
        int col = j * 8 + 2 * t;
        float b0v = eb2[bx * H2_ + col], b1v = eb2[bx * H2_ + col + 1];
        *(uint32_t*)(smem + SM_H2 + swz64(row, col >> 3) + (col & 7) * 2) =
            pack_relu(fmaf(acc2[i][j][0], QINV2, b0v),
                      fmaf(acc2[i][j][1], QINV2, b1v));
        *(uint32_t*)(smem + SM_H2 + swz64(row + 8, col >> 3) + (col & 7) * 2) =
            pack_relu(fmaf(acc2[i][j][2], QINV2, b0v),
                      fmaf(acc2[i][j][3], QINV2, b1v));
      }
    }
    __syncthreads();

    // ---- expert L3: per-row dot64 + sigmoid -> g_Eo[e][b] ----
    {
      float logit = eb3_s[0];
#pragma unroll
      for (int ch = 0; ch < 8; ch++) {
        uint4 v = *(const uint4*)(smem + SM_H2 + swz64(tid, ch));
        const __nv_bfloat162* p = (const __nv_bfloat162*)&v;
#pragma unroll
        for (int q = 0; q < 4; q++) {
          float2 f = __bfloat1622float2(p[q]);
          logit += f.x * ew3_s[ch * 8 + 2 * q] + f.y * ew3_s[ch * 8 + 2 * q + 1];
        }
      }
      g_Eo[(size_t)bx * B_ + m0 + tid] = 1.f / (1.f + __expf(-logit));
    }
  } else {
    // ---- router epilogue: cols [0,64) live (nW==0 warps) -> hs fp32 ----
    float* hs = (float*)(smem + SM_HS);
    if (nW == 0) {
#pragma unroll
      for (int i = 0; i < 4; i++) {
#pragma unroll
        for (int j = 0; j < 8; j++) {
          int row = mW * 64 + i * 16 + g;
          int col = j * 8 + 2 * t;
          float b0v = g_bcat[n0 + col], b1v = g_bcat[n0 + col + 1];
          hs[row * HS_STR + col] = fmaxf(fmaf(acc[i][j][0], QINV, b0v), 0.f);
          hs[row * HS_STR + col + 1] = fmaxf(fmaf(acc[i][j][1], QINV, b1v), 0.f);
          hs[(row + 8) * HS_STR + col] =
              fmaxf(fmaf(acc[i][j][2], QINV, b0v), 0.f);
          hs[(row + 8) * HS_STR + col + 1] =
              fmaxf(fmaf(acc[i][j][3], QINV, b1v), 0.f);
        }
      }
    }
    // ---- load router tail weights ----
    float* rW2_s = (float*)(smem + SM_RW2);
    float* rW3_s = (float*)(smem + SM_RW3);
    float* rb2_s = (float*)(smem + SM_RB2);
    float* rb3_s = (float*)(smem + SM_RB3);
#pragma unroll
    for (int i = 0; i < 16; i++) rW2_s[tid + 128 * i] = rW2[tid + 128 * i];
#pragma unroll
    for (int i = 0; i < 4; i++) rW3_s[tid + 128 * i] = rW3[tid + 128 * i];
    if (tid < R2_) rb2_s[tid] = rb2[tid];
    if (tid < E_) rb3_s[tid] = rb3[tid];
    __syncthreads();

    // ---- per-row MLP tail + softmax -> out routing_weights ----
    for (int rr = 0; rr < 32; ++rr) {
      int row = wid * 32 + rr;
      const float* hrow = hs + row * HS_STR;
      float d1 = rb2_s[lane];
#pragma unroll
      for (int k = 0; k < R1_; k++) d1 += hrow[k] * rW2_s[k * R2_ + lane];
      d1 = fmaxf(d1, 0.f);

      float d2 = (lane < E_) ? rb3_s[lane] : 0.f;
#pragma unroll
      for (int k = 0; k < R2_; k++) {
        float v = __shfl_sync(0xffffffffu, d1, k);
        if (lane < E_) d2 += v * rW3_s[k * E_ + lane];
      }
      float mx = d2;
#pragma unroll
      for (int off = 8; off > 0; off >>= 1)
        mx = fmaxf(mx, __shfl_xor_sync(0xffffffffu, mx, off, 16));
      float ex = __expf(d2 - mx);
      float s = ex;
#pragma unroll
      for (int off = 8; off > 0; off >>= 1)
        s += __shfl_xor_sync(0xffffffffu, s, off, 16);
      if (lane < E_)
        out[(size_t)B_ + (size_t)(m0 + row) * E_ + lane] = ex / s;
    }
  }
}

// ---------------- k_mix: pred = sum_e rw*eo; write expert_outputs --------
__global__ __launch_bounds__(256) void k_mix(float* __restrict__ out) {
  int b = blockIdx.x * 256 + threadIdx.x;
  const float4* rwp = (const float4*)(out + (size_t)B_ + (size_t)b * E_);
  float4 r0 = rwp[0], r1 = rwp[1], r2 = rwp[2], r3 = rwp[3];
  float eo[E_];
#pragma unroll
  for (int e = 0; e < E_; e++) eo[e] = g_Eo[(size_t)e * B_ + b];
  float p = r0.x * eo[0] + r0.y * eo[1] + r0.z * eo[2] + r0.w * eo[3] +
            r1.x * eo[4] + r1.y * eo[5] + r1.z * eo[6] + r1.w * eo[7] +
            r2.x * eo[8] + r2.y * eo[9] + r2.z * eo[10] + r2.w * eo[11] +
            r3.x * eo[12] + r3.y * eo[13] + r3.z * eo[14] + r3.w * eo[15];
  out[b] = p;
  float4* eop = (float4*)(out + (size_t)B_ + (size_t)B_ * E_ + (size_t)b * E_);
#pragma unroll
  for (int q = 0; q < 4; q++)
    eop[q] = make_float4(eo[4 * q], eo[4 * q + 1], eo[4 * q + 2], eo[4 * q + 3]);
}

// ---------------- launch ----------------
extern "C" void kernel_launch(void* const* d_in, const int* in_sizes, int n_in,
                              void* d_out, int out_size) {
  const float* x     = (const float*)d_in[0];
  const float* rg    = (const float*)d_in[1];
  const float* rbta  = (const float*)d_in[2];
  const float* rm    = (const float*)d_in[3];
  const float* rv    = (const float*)d_in[4];
  const float* rW1   = (const float*)d_in[5];
  const float* rb1   = (const float*)d_in[6];
  const float* rW2   = (const float*)d_in[7];
  const float* rb2   = (const float*)d_in[8];
  const float* rW3   = (const float*)d_in[9];
  const float* rb3   = (const float*)d_in[10];
  const float* eg    = (const float*)d_in[11];
  const float* ebt   = (const float*)d_in[12];
  const float* em    = (const float*)d_in[13];
  const float* ev    = (const float*)d_in[14];
  const float* eW1   = (const float*)d_in[15];
  const float* eb1   = (const float*)d_in[16];
  const float* eW2   = (const float*)d_in[17];
  const float* eb2   = (const float*)d_in[18];
  const float* eW3   = (const float*)d_in[19];
  const float* eb3   = (const float*)d_in[20];
  float* out = (float*)d_out;

  cudaFuncSetAttribute(k_gemm_f, cudaFuncAttributeMaxDynamicSharedMemorySize,
                       SM_TOT);

  k_prep<<<PREP_FOLD + PREP_W2T + PREP_CVT, 256>>>(
      x, rg, rbta, rm, rv, rW1, rb1, eg, ebt, em, ev, eW1, eb1, eW2);
  k_gemm_f<<<dim3(E_ + 1, B_ / 128), 128, SM_TOT>>>(eb2, eW3, eb3,
                                                    rW2, rb2, rW3, rb3, out);
  k_mix<<<B_ / 256, 256>>>(out);
}